// round 15
// baseline (speedup 1.0000x reference)
#include <cuda_runtime.h>
#include <cuda_bf16.h>
#include <math.h>
#include <stdint.h>

// ---------------- problem constants ----------------
#define Bb   32
#define SEQ  512
#define EE   128
#define HH   8
#define EHH  1024
#define LL   3
#define TOK  (Bb*SEQ)      // 16384 tokens
#define BHH  (Bb*HH)       // 256 (b,h) pairs
#define KF   101
#define ADIM 200
#define SCALE 0.08838834764831845f

// ---------------- device scratch ----------------
__device__ float g_x    [(size_t)TOK*EE];
__device__ float g_xinit[(size_t)TOK*EE];
__device__ float g_out1 [(size_t)TOK*EE];
__device__ float g_out2 [(size_t)TOK*EE];
__device__ float g_w    [TOK];
__device__ float g_v    [(size_t)BHH*SEQ*EE];

// packed bf16 hi/lo activation planes ([rows][K/2] uint32 words)
__device__ uint32_t g_xnh [(size_t)TOK*64],  g_xnl [(size_t)TOK*64];
__device__ uint32_t g_qh  [(size_t)BHH*SEQ*64], g_ql[(size_t)BHH*SEQ*64];
__device__ uint32_t g_kh  [(size_t)BHH*SEQ*64], g_kl[(size_t)BHH*SEQ*64];
__device__ uint32_t g_vth [(size_t)BHH*EE*256], g_vtl[(size_t)BHH*EE*256]; // V^T packed [bh][d][tokpair]
__device__ uint32_t g_valsh[(size_t)TOK*512], g_valsl[(size_t)TOK*512];

// packed weight planes ([N][K/2], per layer)
__device__ uint32_t g_Wqkvh[(size_t)LL*3072*64],  g_Wqkvl[(size_t)LL*3072*64];
__device__ uint32_t g_Wffnh[(size_t)LL*128*64],   g_Wffnl[(size_t)LL*128*64];

// combined o_W@out_W weight: fp32 staging + packed planes + combined bias
__device__ float    g_Wc  [(size_t)LL*EHH*EE];
__device__ float    g_bc  [(size_t)LL*EE];
__device__ uint32_t g_Wch [(size_t)LL*128*512], g_Wcl[(size_t)LL*128*512];

// ---------------- helpers ----------------
__device__ __forceinline__ float blkSum128(float v, float* sm) {
    #pragma unroll
    for (int o = 16; o > 0; o >>= 1) v += __shfl_xor_sync(0xffffffffu, v, o);
    int w = threadIdx.x >> 5;
    if ((threadIdx.x & 31) == 0) sm[w] = v;
    __syncthreads();
    float r = sm[0] + sm[1] + sm[2] + sm[3];
    __syncthreads();
    return r;
}

__device__ __forceinline__ void bsplit2(float x, float y, uint32_t& hi, uint32_t& lo) {
    __nv_bfloat16 xh = __float2bfloat16(x);
    __nv_bfloat16 yh = __float2bfloat16(y);
    float xr = x - __bfloat162float(xh);
    float yr = y - __bfloat162float(yh);
    __nv_bfloat162 h2 = __halves2bfloat162(xh, yh);
    __nv_bfloat162 l2 = __halves2bfloat162(__float2bfloat16(xr), __float2bfloat16(yr));
    hi = *reinterpret_cast<uint32_t*>(&h2);
    lo = *reinterpret_cast<uint32_t*>(&l2);
}

__device__ __forceinline__ void mma_bf16(float* d, const uint32_t* a,
                                         uint32_t b0, uint32_t b1) {
    asm volatile(
        "mma.sync.aligned.m16n8k16.row.col.f32.bf16.bf16.f32 "
        "{%0,%1,%2,%3}, {%4,%5,%6,%7}, {%8,%9}, {%0,%1,%2,%3};\n"
        : "+f"(d[0]), "+f"(d[1]), "+f"(d[2]), "+f"(d[3])
        : "r"(a[0]), "r"(a[1]), "r"(a[2]), "r"(a[3]), "r"(b0), "r"(b1));
}

__device__ __forceinline__ void cp16(uint32_t* sdst, const uint32_t* gsrc) {
    uint32_t s = (uint32_t)__cvta_generic_to_shared(sdst);
    asm volatile("cp.async.ca.shared.global [%0], [%1], 16;" :: "r"(s), "l"(gsrc));
}

// ---------------- weight split: W[K][N] float -> planes [N][K/2]; y = layer ----------------
__global__ void split_weights_kernel(const float* __restrict__ W,
                                     uint32_t* __restrict__ oh,
                                     uint32_t* __restrict__ ol,
                                     int K, int N) {
    int kw = K >> 1;
    size_t lw = (size_t)N*kw;
    int L = blockIdx.y;
    W  += (size_t)L*K*N;
    oh += (size_t)L*lw;
    ol += (size_t)L*lw;
    int idx = blockIdx.x*256 + threadIdx.x;
    if (idx >= N*kw) return;
    int n = idx % N, kp = idx / N;
    float w0 = W[(size_t)(2*kp)*N + n];
    float w1 = W[(size_t)(2*kp+1)*N + n];
    uint32_t hi, lo; bsplit2(w0, w1, hi, lo);
    oh[(size_t)n*kw + kp] = hi;
    ol[(size_t)n*kw + kp] = lo;
}

// ---------------- combined weight precompute: Wc = o_W @ out_W (fp32) ----------------
__global__ void combine_w_kernel(const float* __restrict__ oW,
                                 const float* __restrict__ outW) {
    int L = blockIdx.y;
    int k = blockIdx.x;
    int n = threadIdx.x;
    const float* ow = oW  + (size_t)L*EHH*EHH + (size_t)k*EHH;
    const float* uw = outW + (size_t)L*EHH*EE;
    __shared__ float so[EHH];
    for (int j = threadIdx.x; j < EHH; j += EE) so[j] = ow[j];
    __syncthreads();
    float acc = 0.f;
    #pragma unroll 8
    for (int j = 0; j < EHH; j++) acc = fmaf(so[j], uw[(size_t)j*EE + n], acc);
    g_Wc[(size_t)L*EHH*EE + (size_t)k*EE + n] = acc;
}

// bc = o_b @ out_W + out_b
__global__ void combine_b_kernel(const float* __restrict__ ob,
                                 const float* __restrict__ outW,
                                 const float* __restrict__ outb) {
    int L = blockIdx.x;
    int n = threadIdx.x;
    const float* uw = outW + (size_t)L*EHH*EE;
    const float* obl = ob + (size_t)L*EHH;
    float acc = outb[(size_t)L*EE + n];
    #pragma unroll 8
    for (int j = 0; j < EHH; j++) acc = fmaf(obl[j], uw[(size_t)j*EE + n], acc);
    g_bc[(size_t)L*EE + n] = acc;
}

// ---------------- embed ----------------
__global__ void embed_kernel(const float* __restrict__ str_fea,
                             const int*   __restrict__ comp_fea,
                             const float* __restrict__ atom_table,
                             const float* __restrict__ comp_W,
                             const float* __restrict__ comp_b,
                             const float* __restrict__ pdd_W,
                             const float* __restrict__ pdd_b) {
    int t = blockIdx.x;
    int e = threadIdx.x;
    __shared__ float sa[ADIM];
    __shared__ float ss[KF-1];
    const float* sf = str_fea + (size_t)t*KF;
    int idx = comp_fea[t];
    const float* at = atom_table + (size_t)idx*ADIM;
    for (int j = e; j < ADIM; j += EE) sa[j] = at[j];
    for (int j = e; j < KF-1; j += EE) ss[j] = sf[1+j];
    if (e == 0) g_w[t] = sf[0];
    __syncthreads();
    float acc = comp_b[e] + pdd_b[e];
    #pragma unroll 4
    for (int a = 0; a < ADIM; a++) acc = fmaf(sa[a], comp_W[a*EE + e], acc);
    #pragma unroll 4
    for (int j = 0; j < KF-1; j++) acc = fmaf(ss[j], pdd_W[j*EE + e], acc);
    g_x[(size_t)t*EE + e]     = acc;
    g_xinit[(size_t)t*EE + e] = acc;
}

// ---------------- warp-per-token layernorm; PACKED=1 -> bf16 hi/lo planes ----------------
template<int PACKED>
__global__ void ln_kernel(const float* __restrict__ src1,
                          const float* __restrict__ src2,
                          const float* __restrict__ gam,
                          const float* __restrict__ bet,
                          float* __restrict__ dstf,
                          uint32_t* __restrict__ dsth,
                          uint32_t* __restrict__ dstl) {
    int warp = threadIdx.x >> 5, lane = threadIdx.x & 31;
    int t = blockIdx.x*4 + warp;
    size_t off = (size_t)t*EE + lane*4;
    float4 v = *(const float4*)&src1[off];
    if (src2) {
        const float4 u = *(const float4*)&src2[off];
        v.x += u.x; v.y += u.y; v.z += u.z; v.w += u.w;
    }
    float s = v.x + v.y + v.z + v.w;
    #pragma unroll
    for (int o = 16; o > 0; o >>= 1) s += __shfl_xor_sync(0xffffffffu, s, o);
    float m = s * (1.f/EE);
    float dx = v.x - m, dy = v.y - m, dz = v.z - m, dw = v.w - m;
    float q = dx*dx + dy*dy + dz*dz + dw*dw;
    #pragma unroll
    for (int o = 16; o > 0; o >>= 1) q += __shfl_xor_sync(0xffffffffu, q, o);
    float rstd = rsqrtf(q * (1.f/EE) + 1e-5f);
    const float4 gv = *(const float4*)&gam[lane*4];
    const float4 bv = *(const float4*)&bet[lane*4];
    float r0 = dx*rstd*gv.x + bv.x;
    float r1 = dy*rstd*gv.y + bv.y;
    float r2 = dz*rstd*gv.z + bv.z;
    float r3 = dw*rstd*gv.w + bv.w;
    if (PACKED) {
        uint32_t h0, l0, h1, l1;
        bsplit2(r0, r1, h0, l0);
        bsplit2(r2, r3, h1, l1);
        *(uint2*)&dsth[(size_t)t*64 + lane*2] = make_uint2(h0, h1);
        *(uint2*)&dstl[(size_t)t*64 + lane*2] = make_uint2(l0, l1);
    } else {
        *(float4*)&dstf[off] = make_float4(r0, r1, r2, r3);
    }
}

// ---------------- V transpose+split: g_v [bh][tok][d] -> packed [bh][d][tokpair] ----------------
__global__ void transpose_v_kernel() {
    __shared__ float sv[64][129];
    int bh = blockIdx.y, t0 = blockIdx.x*64;
    int tid = threadIdx.x;
    const float* Vg = g_v + ((size_t)bh*SEQ + t0)*EE;
    #pragma unroll
    for (int i = 0; i < 8; i++) {
        int c = i*256 + tid;               // 0..2047 float4s
        int tok = c >> 5, q = (c & 31)*4;
        const float4 f = *(const float4*)&Vg[(size_t)tok*EE + q];
        sv[tok][q]   = f.x; sv[tok][q+1] = f.y;
        sv[tok][q+2] = f.z; sv[tok][q+3] = f.w;
    }
    __syncthreads();
    uint32_t* oh = g_vth + (size_t)bh*EE*256 + (t0 >> 1);
    uint32_t* ol = g_vtl + (size_t)bh*EE*256 + (t0 >> 1);
    #pragma unroll
    for (int i = 0; i < 16; i++) {
        int widx = i*256 + tid;            // 0..4095
        int d = widx >> 5, tp = widx & 31;
        uint32_t hi, lo;
        bsplit2(sv[2*tp][d], sv[2*tp+1][d], hi, lo);
        oh[(size_t)d*256 + tp] = hi;
        ol[(size_t)d*256 + tp] = lo;
    }
}

// ---------------- pre-split bf16 GEMM (3-mma), cp.async double-buffered ----------------
#define BM 128
#define BN 128
#define GP 20   // smem row pitch in words
#define PL 2560 // plane size: 128*GP

enum { EPI_BIAS_ADD=1, EPI_MISH=2, EPI_QKV=3 };

template<int EPI>
__global__ __launch_bounds__(256, 2)
void gemm_kernel(const uint32_t* __restrict__ Ah_g, const uint32_t* __restrict__ Al_g, int lda,
                 const uint32_t* __restrict__ Bh_g, const uint32_t* __restrict__ Bl_g, int ldb,
                 float* __restrict__ C, int ldc,
                 int K,
                 const float* __restrict__ bias,
                 const float* __restrict__ addend) {
    extern __shared__ uint32_t smx[];
    int bm = blockIdx.y * BM, bn = blockIdx.x * BN;

    int tid  = threadIdx.x;
    int lane = tid & 31;
    int wid  = tid >> 5;
    int warpM = wid & 3;
    int warpN = wid >> 2;
    int g  = lane >> 2;
    int tg = lane & 3;

    float d[2][8][4];
    #pragma unroll
    for (int mt=0; mt<2; mt++)
        #pragma unroll
        for (int nt=0; nt<8; nt++)
            #pragma unroll
            for (int c=0; c<4; c++) d[mt][nt][c] = 0.f;

    int nIter = K >> 5;

    {
        uint32_t* s = smx;
        #pragma unroll
        for (int i = 0; i < 2; i++) {
            int c = i*256 + tid;
            int row = c >> 2, q = (c & 3)*4;
            cp16(&s[0*PL + row*GP + q], Ah_g + (size_t)(bm+row)*lda + q);
            cp16(&s[1*PL + row*GP + q], Al_g + (size_t)(bm+row)*lda + q);
            cp16(&s[2*PL + row*GP + q], Bh_g + (size_t)(bn+row)*ldb + q);
            cp16(&s[3*PL + row*GP + q], Bl_g + (size_t)(bn+row)*ldb + q);
        }
    }
    asm volatile("cp.async.commit_group;" ::: "memory");

    for (int it = 0; it < nIter; it++) {
        asm volatile("cp.async.wait_group 0;" ::: "memory");
        __syncthreads();
        if (it + 1 < nIter) {
            uint32_t* s = smx + ((it+1)&1)*4*PL;
            int kw = (it+1)*16;
            #pragma unroll
            for (int i = 0; i < 2; i++) {
                int c = i*256 + tid;
                int row = c >> 2, q = (c & 3)*4;
                cp16(&s[0*PL + row*GP + q], Ah_g + (size_t)(bm+row)*lda + kw + q);
                cp16(&s[1*PL + row*GP + q], Al_g + (size_t)(bm+row)*lda + kw + q);
                cp16(&s[2*PL + row*GP + q], Bh_g + (size_t)(bn+row)*ldb + kw + q);
                cp16(&s[3*PL + row*GP + q], Bl_g + (size_t)(bn+row)*ldb + kw + q);
            }
            asm volatile("cp.async.commit_group;" ::: "memory");
        }

        const uint32_t* Ah = smx + (it&1)*4*PL;
        const uint32_t* Al = Ah + PL;
        const uint32_t* Bh = Al + PL;
        const uint32_t* Bl = Bh + PL;

        #pragma unroll
        for (int js = 0; js < 2; js++) {
            int kb = js*8 + tg;
            uint32_t ah[2][4], al[2][4];
            #pragma unroll
            for (int mt = 0; mt < 2; mt++) {
                int m0 = warpM*32 + mt*16 + g;
                ah[mt][0] = Ah[m0*GP + kb];       al[mt][0] = Al[m0*GP + kb];
                ah[mt][1] = Ah[(m0+8)*GP + kb];   al[mt][1] = Al[(m0+8)*GP + kb];
                ah[mt][2] = Ah[m0*GP + kb+4];     al[mt][2] = Al[m0*GP + kb+4];
                ah[mt][3] = Ah[(m0+8)*GP + kb+4]; al[mt][3] = Al[(m0+8)*GP + kb+4];
            }
            #pragma unroll
            for (int nt = 0; nt < 8; nt++) {
                int n0 = warpN*64 + nt*8 + g;
                uint32_t bh0 = Bh[n0*GP + kb], bh1 = Bh[n0*GP + kb+4];
                uint32_t bl0 = Bl[n0*GP + kb], bl1 = Bl[n0*GP + kb+4];
                #pragma unroll
                for (int mt = 0; mt < 2; mt++) {
                    mma_bf16(d[mt][nt], ah[mt], bh0, bh1);
                    mma_bf16(d[mt][nt], ah[mt], bl0, bl1);
                    mma_bf16(d[mt][nt], al[mt], bh0, bh1);
                }
            }
        }
    }

    #pragma unroll
    for (int mt = 0; mt < 2; mt++) {
        #pragma unroll
        for (int nt = 0; nt < 8; nt++) {
            #pragma unroll
            for (int half = 0; half < 2; half++) {
                int m = bm + warpM*32 + mt*16 + g + half*8;
                int n = bn + warpN*64 + nt*8 + 2*tg;
                float v0 = d[mt][nt][half*2 + 0];
                float v1 = d[mt][nt][half*2 + 1];
                if (EPI == EPI_BIAS_ADD) {
                    const float2 ad = *(const float2*)&addend[(size_t)m*ldc + n];
                    float2 r = make_float2(v0 + bias[n] + ad.x, v1 + bias[n+1] + ad.y);
                    *(float2*)&C[(size_t)m*ldc + n] = r;
                } else if (EPI == EPI_MISH) {
                    float x0 = v0 + bias[n],  x1 = v1 + bias[n+1];
                    float s0 = (x0 > 20.f) ? x0 : log1pf(expf(x0));
                    float s1 = (x1 > 20.f) ? x1 : log1pf(expf(x1));
                    float2 r = make_float2(x0 * tanhf(s0), x1 * tanhf(s1));
                    *(float2*)&C[(size_t)m*ldc + n] = r;
                } else { // EPI_QKV
                    int b = m >> 9, tok = m & 511;
                    int hh = n / 384, rem = n % 384;
                    int rr = rem >> 7, dd = rem & 127;
                    size_t bhrow = ((size_t)(b*HH + hh)*SEQ + tok);
                    float x0 = v0 + bias[n], x1 = v1 + bias[n+1];
                    if (rr == 0) {
                        uint32_t hi, lo; bsplit2(x0*SCALE, x1*SCALE, hi, lo);
                        g_qh[bhrow*64 + (dd>>1)] = hi;
                        g_ql[bhrow*64 + (dd>>1)] = lo;
                    } else if (rr == 1) {
                        uint32_t hi, lo; bsplit2(x0, x1, hi, lo);
                        g_kh[bhrow*64 + (dd>>1)] = hi;
                        g_kl[bhrow*64 + (dd>>1)] = lo;
                    } else {
                        *(float2*)&g_v[bhrow*EE + dd] = make_float2(x0, x1);
                    }
                }
            }
        }
    }
}

// ---------------- fused flash attention (16-key tiles, cp.async double-buffered, 2 CTAs/SM) ----------------
#define QP 68   // pitch for [row][d-pair] Q/K tiles
#define VP 12   // pitch for [d][key-pair] V tiles (8 data + 4 pad)
#define KT 16
#define NKT (SEQ/KT)   // 32

// word offsets
#define OFF_Q  0
#define QPLANE (128*QP)            // 8704
#define OFF_K  (2*QPLANE)          // 17408
#define KPLANE (KT*QP)             // 1088
#define KSTG   (2*KPLANE)          // 2176 (hi+lo)
#define OFF_V  (OFF_K + 2*KSTG)    // 21760
#define VPLANE (128*VP)            // 1536
#define VSTG   (2*VPLANE)          // 3072
#define OFF_WS (OFF_V + 2*VSTG)    // 27904
#define FLASH_WORDS (OFF_WS + 2*KT) // 27936 words = 111744 B

__global__ __launch_bounds__(256, 2)
void flash_kernel() {
    extern __shared__ uint32_t smx[];
    uint32_t* Qh = smx + OFF_Q;
    uint32_t* Ql = Qh + QPLANE;
    float*    ws = (float*)(smx + OFF_WS);

    int qt = blockIdx.x, bh = blockIdx.y;
    int b = bh >> 3, h = bh & 7;
    int tid = threadIdx.x;
    int lane = tid & 31;
    int wid = tid >> 5;
    int g = lane >> 2, tg = lane & 3;

    const uint32_t* Qgh = g_qh + ((size_t)bh*SEQ + qt*128)*64;
    const uint32_t* Qgl = g_ql + ((size_t)bh*SEQ + qt*128)*64;
    const uint32_t* Kbh = g_kh + (size_t)bh*SEQ*64;
    const uint32_t* Kbl = g_kl + (size_t)bh*SEQ*64;
    const uint32_t* Vbh = g_vth + (size_t)bh*EE*256;
    const uint32_t* Vbl = g_vtl + (size_t)bh*EE*256;

    // ---- prologue: async-load Q tile + tile 0 (group 0) ----
    #pragma unroll
    for (int i = 0; i < 8; i++) {
        int c = i*256 + tid;               // 0..2047
        int row = c >> 4, q = (c & 15)*4;
        cp16(&Qh[row*QP + q], Qgh + (size_t)row*64 + q);
        cp16(&Ql[row*QP + q], Qgl + (size_t)row*64 + q);
    }
    {
        // K tile 0: 16 rows x 16 uint4 per plane
        int row = tid >> 4, q = (tid & 15)*4;
        uint32_t* ks = smx + OFF_K;
        cp16(&ks[row*QP + q],          Kbh + (size_t)row*64 + q);
        cp16(&ks[KPLANE + row*QP + q], Kbl + (size_t)row*64 + q);
        // V tile 0: 128 d x 2 uint4 per plane
        int dd = tid >> 1, vq = (tid & 1)*4;
        uint32_t* vs = smx + OFF_V;
        cp16(&vs[dd*VP + vq],          Vbh + (size_t)dd*256 + vq);
        cp16(&vs[VPLANE + dd*VP + vq], Vbl + (size_t)dd*256 + vq);
        if (tid < KT) ws[tid] = g_w[b*SEQ + tid];
    }
    asm volatile("cp.async.commit_group;" ::: "memory");

    int rowg = qt*128 + wid*16 + g;
    bool mq0 = g_w[b*SEQ + rowg]     > 0.f;
    bool mq1 = g_w[b*SEQ + rowg + 8] > 0.f;

    float m_run[2] = {-9.0e15f, -9.0e15f};
    float l_run[2] = {0.f, 0.f};
    float o[16][4];
    #pragma unroll
    for (int dt = 0; dt < 16; dt++)
        #pragma unroll
        for (int c = 0; c < 4; c++) o[dt][c] = 0.f;

    int m0 = wid*16 + g;

    for (int kt = 0; kt < NKT; kt++) {
        // issue next tile's loads into the other stage
        if (kt + 1 < NKT) {
            int st = (kt + 1) & 1;
            int row = tid >> 4, q = (tid & 15)*4;
            uint32_t* ks = smx + OFF_K + st*KSTG;
            cp16(&ks[row*QP + q],          Kbh + ((size_t)(kt+1)*KT + row)*64 + q);
            cp16(&ks[KPLANE + row*QP + q], Kbl + ((size_t)(kt+1)*KT + row)*64 + q);
            int dd = tid >> 1, vq = (tid & 1)*4;
            uint32_t* vs = smx + OFF_V + st*VSTG;
            cp16(&vs[dd*VP + vq],          Vbh + (size_t)dd*256 + (kt+1)*8 + vq);
            cp16(&vs[VPLANE + dd*VP + vq], Vbl + (size_t)dd*256 + (kt+1)*8 + vq);
            if (tid < KT) ws[st*KT + tid] = g_w[b*SEQ + (kt+1)*KT + tid];
            asm volatile("cp.async.commit_group;" ::: "memory");
            asm volatile("cp.async.wait_group 1;" ::: "memory");
        } else {
            asm volatile("cp.async.wait_group 0;" ::: "memory");
        }
        __syncthreads();

        int st = kt & 1;
        const uint32_t* Kh = smx + OFF_K + st*KSTG;
        const uint32_t* Kl = Kh + KPLANE;
        const uint32_t* Vh = smx + OFF_V + st*VSTG;
        const uint32_t* Vl = Vh + VPLANE;
        const float* wss = ws + st*KT;

        // ---- S = Q @ K^T (warp: 16 rows x 16 keys) ----
        float s[2][4];
        #pragma unroll
        for (int nt=0; nt<2; nt++)
            #pragma unroll
            for (int c=0; c<4; c++) s[nt][c] = 0.f;

        #pragma unroll
        for (int ks = 0; ks < 8; ks++) {
            int kb = ks*8 + tg;
            uint32_t ah[4], al[4];
            ah[0] = Qh[m0*QP + kb];       al[0] = Ql[m0*QP + kb];
            ah[1] = Qh[(m0+8)*QP + kb];   al[1] = Ql[(m0+8)*QP + kb];
            ah[2] = Qh[m0*QP + kb+4];     al[2] = Ql[m0*QP + kb+4];
            ah[3] = Qh[(m0+8)*QP + kb+4]; al[3] = Ql[(m0+8)*QP + kb+4];
            #pragma unroll
            for (int nt = 0; nt < 2; nt++) {
                int n0 = nt*8 + g;
                uint32_t bh0 = Kh[n0*QP + kb], bh1 = Kh[n0*QP + kb+4];
                uint32_t bl0 = Kl[n0*QP + kb], bl1 = Kl[n0*QP + kb+4];
                mma_bf16(s[nt], ah, bh0, bh1);
                mma_bf16(s[nt], ah, bl0, bl1);
                mma_bf16(s[nt], al, bh0, bh1);
            }
        }

        // ---- mask + online softmax ----
        float tmax[2] = {-9.0e15f, -9.0e15f};
        #pragma unroll
        for (int nt = 0; nt < 2; nt++) {
            int col0 = nt*8 + 2*tg;
            #pragma unroll
            for (int c = 0; c < 4; c++) {
                bool mk = wss[col0 + (c & 1)] > 0.f;
                bool mr = (c < 2) ? mq0 : mq1;
                float v = (mk && mr) ? s[nt][c] : -9.0e15f;
                s[nt][c] = v;
                tmax[c >> 1] = fmaxf(tmax[c >> 1], v);
            }
        }
        #pragma unroll
        for (int off = 1; off <= 2; off <<= 1) {
            tmax[0] = fmaxf(tmax[0], __shfl_xor_sync(0xffffffffu, tmax[0], off));
            tmax[1] = fmaxf(tmax[1], __shfl_xor_sync(0xffffffffu, tmax[1], off));
        }
        float nm0 = fmaxf(m_run[0], tmax[0]);
        float nm1 = fmaxf(m_run[1], tmax[1]);
        float a0 = __expf(m_run[0] - nm0);
        float a1 = __expf(m_run[1] - nm1);
        float rs[2] = {0.f, 0.f};
        #pragma unroll
        for (int nt = 0; nt < 2; nt++) {
            int col0 = nt*8 + 2*tg;
            #pragma unroll
            for (int c = 0; c < 4; c++) {
                float nm = (c < 2) ? nm0 : nm1;
                float p = wss[col0 + (c & 1)] * __expf(s[nt][c] - nm);
                s[nt][c] = p;
                rs[c >> 1] += p;
            }
        }
        #pragma unroll
        for (int off = 1; off <= 2; off <<= 1) {
            rs[0] += __shfl_xor_sync(0xffffffffu, rs[0], off);
            rs[1] += __shfl_xor_sync(0xffffffffu, rs[1], off);
        }
        l_run[0] = a0*l_run[0] + rs[0];
        l_run[1] = a1*l_run[1] + rs[1];
        m_run[0] = nm0; m_run[1] = nm1;
        #pragma unroll
        for (int dt = 0; dt < 16; dt++) {
            o[dt][0] *= a0; o[dt][1] *= a0;
            o[dt][2] *= a1; o[dt][3] *= a1;
        }

        // ---- O += P @ V (single k16 step over 16 keys) ----
        {
            uint32_t pah[4], pal[4];
            bsplit2(s[0][0], s[0][1], pah[0], pal[0]);
            bsplit2(s[0][2], s[0][3], pah[1], pal[1]);
            bsplit2(s[1][0], s[1][1], pah[2], pal[2]);
            bsplit2(s[1][2], s[1][3], pah[3], pal[3]);
            #pragma unroll
            for (int dt = 0; dt < 16; dt++) {
                int n0 = dt*8 + g;
                uint32_t vh0 = Vh[n0*VP + tg], vh1 = Vh[n0*VP + tg+4];
                uint32_t vl0 = Vl[n0*VP + tg], vl1 = Vl[n0*VP + tg+4];
                mma_bf16(o[dt], pah, vh0, vh1);
                mma_bf16(o[dt], pah, vl0, vl1);
                mma_bf16(o[dt], pal, vh0, vh1);
            }
        }
        __syncthreads();   // stage reuse barrier before next iteration's loads
    }

    // ---- normalize + store split vals planes ----
    float inv0 = 1.f / l_run[0];
    float inv1 = 1.f / l_run[1];
    size_t r0 = (size_t)(b*SEQ) + qt*128 + wid*16 + g;
    size_t r1 = r0 + 8;
    #pragma unroll
    for (int dt = 0; dt < 16; dt++) {
        int w = h*64 + dt*4 + tg;
        uint32_t hi, lo;
        bsplit2(o[dt][0]*inv0, o[dt][1]*inv0, hi, lo);
        g_valsh[r0*512 + w] = hi; g_valsl[r0*512 + w] = lo;
        bsplit2(o[dt][2]*inv1, o[dt][3]*inv1, hi, lo);
        g_valsh[r1*512 + w] = hi; g_valsl[r1*512 + w] = lo;
    }
}

// ---------------- final: weighted pool + LN + head ----------------
__global__ void pool_head_kernel(const float* __restrict__ ln2_g,
                                 const float* __restrict__ ln2_b,
                                 const float* __restrict__ head_W,
                                 const float* __restrict__ head_b,
                                 float* __restrict__ out) {
    __shared__ float sm[4];
    int b = blockIdx.x, e = threadIdx.x;
    const float* xb  = g_x     + (size_t)b*SEQ*EE;
    const float* xib = g_xinit + (size_t)b*SEQ*EE;
    float s = 0.f;
    for (int n = 0; n < SEQ; n++)
        s = fmaf(g_w[b*SEQ + n], xb[n*EE + e] + xib[n*EE + e], s);
    float m = blkSum128(s, sm) * (1.f/EE);
    float d = s - m;
    float var = blkSum128(d*d, sm) * (1.f/EE);
    float p = d * rsqrtf(var + 1e-5f) * ln2_g[e] + ln2_b[e];
    float dot = blkSum128(p * head_W[e], sm);
    if (e == 0) out[b] = dot + head_b[0];
}

// ---------------- host launch ----------------
#define GEMM_SMEM (2*4*PL*4)

extern "C" void kernel_launch(void* const* d_in, const int* in_sizes, int n_in,
                              void* d_out, int out_size) {
    (void)in_sizes; (void)n_in; (void)out_size;
    const float* str_fea   = (const float*)d_in[0];
    const int*   comp_fea  = (const int*)  d_in[1];
    const float* atom_table= (const float*)d_in[3];
    const float* comp_W    = (const float*)d_in[4];
    const float* comp_b    = (const float*)d_in[5];
    const float* pdd_W     = (const float*)d_in[6];
    const float* pdd_b     = (const float*)d_in[7];
    const float* enc_ln_g  = (const float*)d_in[8];
    const float* enc_ln_b  = (const float*)d_in[9];
    const float* qkv_W     = (const float*)d_in[10];
    const float* qkv_b     = (const float*)d_in[11];
    const float* o_W       = (const float*)d_in[12];
    const float* o_b       = (const float*)d_in[13];
    const float* out_W     = (const float*)d_in[14];
    const float* out_b     = (const float*)d_in[15];
    const float* ffn_W     = (const float*)d_in[16];
    const float* ffn_b     = (const float*)d_in[17];
    const float* ln2_g     = (const float*)d_in[18];
    const float* ln2_b     = (const float*)d_in[19];
    const float* head_W    = (const float*)d_in[20];
    const float* head_b    = (const float*)d_in[21];
    float* out = (float*)d_out;

    void* p;
    cudaGetSymbolAddress(&p, g_x);      float* px    = (float*)p;
    cudaGetSymbolAddress(&p, g_out1);   float* pout1 = (float*)p;
    cudaGetSymbolAddress(&p, g_out2);   float* pout2 = (float*)p;
    cudaGetSymbolAddress(&p, g_xnh);    uint32_t* pxnh = (uint32_t*)p;
    cudaGetSymbolAddress(&p, g_xnl);    uint32_t* pxnl = (uint32_t*)p;
    cudaGetSymbolAddress(&p, g_valsh);  uint32_t* pvalsh = (uint32_t*)p;
    cudaGetSymbolAddress(&p, g_valsl);  uint32_t* pvalsl = (uint32_t*)p;
    cudaGetSymbolAddress(&p, g_Wqkvh);  uint32_t* pWqkvh = (uint32_t*)p;
    cudaGetSymbolAddress(&p, g_Wqkvl);  uint32_t* pWqkvl = (uint32_t*)p;
    cudaGetSymbolAddress(&p, g_Wffnh);  uint32_t* pWffnh = (uint32_t*)p;
    cudaGetSymbolAddress(&p, g_Wffnl);  uint32_t* pWffnl = (uint32_t*)p;
    cudaGetSymbolAddress(&p, g_Wc);     float* pWc = (float*)p;
    cudaGetSymbolAddress(&p, g_bc);     float* pbc = (float*)p;
    cudaGetSymbolAddress(&p, g_Wch);    uint32_t* pWch = (uint32_t*)p;
    cudaGetSymbolAddress(&p, g_Wcl);    uint32_t* pWcl = (uint32_t*)p;

    cudaFuncSetAttribute(flash_kernel,
        cudaFuncAttributeMaxDynamicSharedMemorySize, FLASH_WORDS * 4);
    cudaFuncSetAttribute(gemm_kernel<EPI_BIAS_ADD>,
        cudaFuncAttributeMaxDynamicSharedMemorySize, GEMM_SMEM);
    cudaFuncSetAttribute(gemm_kernel<EPI_MISH>,
        cudaFuncAttributeMaxDynamicSharedMemorySize, GEMM_SMEM);
    cudaFuncSetAttribute(gemm_kernel<EPI_QKV>,
        cudaFuncAttributeMaxDynamicSharedMemorySize, GEMM_SMEM);

    // ---- precompute combined o_W@out_W weight + bias, then split ----
    combine_w_kernel<<<dim3(EHH, LL), EE>>>(o_W, out_W);
    combine_b_kernel<<<LL, EE>>>(o_b, out_W, out_b);
    split_weights_kernel<<<dim3((128*512 + 255)/256, LL), 256>>>(
        pWc, pWch, pWcl, EHH, EE);

    // ---- pre-split remaining weights ----
    split_weights_kernel<<<dim3((3072*64 + 255)/256, LL), 256>>>(
        qkv_W, pWqkvh, pWqkvl, EE, 3*EHH);
    split_weights_kernel<<<dim3((128*64 + 255)/256, LL), 256>>>(
        ffn_W, pWffnh, pWffnl, EE, EE);

    embed_kernel<<<TOK, EE>>>(str_fea, comp_fea, atom_table,
                              comp_W, comp_b, pdd_W, pdd_b);

    for (int i = 0; i < LL; i++) {
        const float* g = enc_ln_g + i*EE;
        const float* bta = enc_ln_b + i*EE;

        // xn = LN(x) -> packed planes
        ln_kernel<1><<<TOK/4, 128>>>(px, nullptr, g, bta, nullptr, pxnh, pxnl);

        // qkv projection -> packed q (scaled) / packed k / float v
        gemm_kernel<EPI_QKV><<<dim3(3*EHH/BN, TOK/BM), 256, GEMM_SMEM>>>(
            pxnh, pxnl, 64,
            pWqkvh + (size_t)i*3072*64, pWqkvl + (size_t)i*3072*64, 64,
            nullptr, 0, EE,
            qkv_b + (size_t)i*3*EHH, nullptr);

        // V -> transposed packed planes
        transpose_v_kernel<<<dim3(SEQ/64, BHH), 256>>>();

        // fused attention -> packed vals planes
        flash_kernel<<<dim3(4, BHH), 256, FLASH_WORDS*4>>>();

        // out1 = x + vals @ (o_W@out_W) + (o_b@out_W + out_b)   [fused projection]
        gemm_kernel<EPI_BIAS_ADD><<<dim3(EE/BN, TOK/BM), 256, GEMM_SMEM>>>(
            pvalsh, pvalsl, 512,
            pWch + (size_t)i*128*512, pWcl + (size_t)i*128*512, 512,
            pout1, EE, EHH,
            pbc + (size_t)i*EE, px);

        // xn = LN(out1) -> packed planes
        ln_kernel<1><<<TOK/4, 128>>>(pout1, nullptr, g, bta, nullptr, pxnh, pxnl);

        // out2 = mish(xn @ ffn_W + ffn_b) (float)
        gemm_kernel<EPI_MISH><<<dim3(EE/BN, TOK/BM), 256, GEMM_SMEM>>>(
            pxnh, pxnl, 64,
            pWffnh + (size_t)i*128*64, pWffnl + (size_t)i*128*64, 64,
            pout2, EE, EE,
            ffn_b + (size_t)i*EE, nullptr);

        // x = LN(out1 + out2) (float)
        ln_kernel<0><<<TOK/4, 128>>>(pout1, pout2, g, bta, px, nullptr, nullptr);
    }

    pool_head_kernel<<<Bb, EE>>>(ln2_g, ln2_b, head_W, head_b, out);
}

// round 16
// speedup vs baseline: 1.0761x; 1.0761x over previous
#include <cuda_runtime.h>
#include <cuda_bf16.h>
#include <math.h>
#include <stdint.h>

// ---------------- problem constants ----------------
#define Bb   32
#define SEQ  512
#define EE   128
#define HH   8
#define EHH  1024
#define LL   3
#define TOK  (Bb*SEQ)      // 16384 tokens
#define BHH  (Bb*HH)       // 256 (b,h) pairs
#define KF   101
#define ADIM 200
#define SCALE 0.08838834764831845f

// ---------------- device scratch ----------------
__device__ float g_x    [(size_t)TOK*EE];
__device__ float g_xinit[(size_t)TOK*EE];
__device__ float g_out1 [(size_t)TOK*EE];
__device__ float g_w    [TOK];
__device__ float g_v    [(size_t)BHH*SEQ*EE];

// packed bf16 hi/lo activation planes ([rows][K/2] uint32 words)
__device__ uint32_t g_xnh [(size_t)TOK*64],  g_xnl [(size_t)TOK*64];
__device__ uint32_t g_qh  [(size_t)BHH*SEQ*64], g_ql[(size_t)BHH*SEQ*64];
__device__ uint32_t g_kh  [(size_t)BHH*SEQ*64], g_kl[(size_t)BHH*SEQ*64];
__device__ uint32_t g_vth [(size_t)BHH*EE*256], g_vtl[(size_t)BHH*EE*256]; // V^T packed [bh][d][tokpair]
__device__ uint32_t g_valsh[(size_t)TOK*512], g_valsl[(size_t)TOK*512];

// packed weight planes ([N][K/2], per layer)
__device__ uint32_t g_Wqkvh[(size_t)LL*3072*64],  g_Wqkvl[(size_t)LL*3072*64];
__device__ uint32_t g_Wffnh[(size_t)LL*128*64],   g_Wffnl[(size_t)LL*128*64];

// combined o_W@out_W weight: fp32 staging + packed planes + combined bias
__device__ float    g_Wc  [(size_t)LL*EHH*EE];
__device__ float    g_bc  [(size_t)LL*EE];
__device__ uint32_t g_Wch [(size_t)LL*128*512], g_Wcl[(size_t)LL*128*512];

// ---------------- helpers ----------------
__device__ __forceinline__ float blkSum128(float v, float* sm) {
    #pragma unroll
    for (int o = 16; o > 0; o >>= 1) v += __shfl_xor_sync(0xffffffffu, v, o);
    int w = threadIdx.x >> 5;
    if ((threadIdx.x & 31) == 0) sm[w] = v;
    __syncthreads();
    float r = sm[0] + sm[1] + sm[2] + sm[3];
    __syncthreads();
    return r;
}

__device__ __forceinline__ void bsplit2(float x, float y, uint32_t& hi, uint32_t& lo) {
    __nv_bfloat16 xh = __float2bfloat16(x);
    __nv_bfloat16 yh = __float2bfloat16(y);
    float xr = x - __bfloat162float(xh);
    float yr = y - __bfloat162float(yh);
    __nv_bfloat162 h2 = __halves2bfloat162(xh, yh);
    __nv_bfloat162 l2 = __halves2bfloat162(__float2bfloat16(xr), __float2bfloat16(yr));
    hi = *reinterpret_cast<uint32_t*>(&h2);
    lo = *reinterpret_cast<uint32_t*>(&l2);
}

__device__ __forceinline__ void mma_bf16(float* d, const uint32_t* a,
                                         uint32_t b0, uint32_t b1) {
    asm volatile(
        "mma.sync.aligned.m16n8k16.row.col.f32.bf16.bf16.f32 "
        "{%0,%1,%2,%3}, {%4,%5,%6,%7}, {%8,%9}, {%0,%1,%2,%3};\n"
        : "+f"(d[0]), "+f"(d[1]), "+f"(d[2]), "+f"(d[3])
        : "r"(a[0]), "r"(a[1]), "r"(a[2]), "r"(a[3]), "r"(b0), "r"(b1));
}

__device__ __forceinline__ void cp16(uint32_t* sdst, const uint32_t* gsrc) {
    uint32_t s = (uint32_t)__cvta_generic_to_shared(sdst);
    asm volatile("cp.async.ca.shared.global [%0], [%1], 16;" :: "r"(s), "l"(gsrc));
}

// ---------------- weight split: W[K][N] float -> planes [N][K/2]; y = layer ----------------
__global__ void split_weights_kernel(const float* __restrict__ W,
                                     uint32_t* __restrict__ oh,
                                     uint32_t* __restrict__ ol,
                                     int K, int N) {
    int kw = K >> 1;
    size_t lw = (size_t)N*kw;
    int L = blockIdx.y;
    W  += (size_t)L*K*N;
    oh += (size_t)L*lw;
    ol += (size_t)L*lw;
    int idx = blockIdx.x*256 + threadIdx.x;
    if (idx >= N*kw) return;
    int n = idx % N, kp = idx / N;
    float w0 = W[(size_t)(2*kp)*N + n];
    float w1 = W[(size_t)(2*kp+1)*N + n];
    uint32_t hi, lo; bsplit2(w0, w1, hi, lo);
    oh[(size_t)n*kw + kp] = hi;
    ol[(size_t)n*kw + kp] = lo;
}

// ---------------- combined weight precompute: Wc = o_W @ out_W (fp32) ----------------
__global__ void combine_w_kernel(const float* __restrict__ oW,
                                 const float* __restrict__ outW) {
    int L = blockIdx.y;
    int k = blockIdx.x;
    int n = threadIdx.x;
    const float* ow = oW  + (size_t)L*EHH*EHH + (size_t)k*EHH;
    const float* uw = outW + (size_t)L*EHH*EE;
    __shared__ float so[EHH];
    for (int j = threadIdx.x; j < EHH; j += EE) so[j] = ow[j];
    __syncthreads();
    float acc = 0.f;
    #pragma unroll 8
    for (int j = 0; j < EHH; j++) acc = fmaf(so[j], uw[(size_t)j*EE + n], acc);
    g_Wc[(size_t)L*EHH*EE + (size_t)k*EE + n] = acc;
}

// bc = o_b @ out_W + out_b
__global__ void combine_b_kernel(const float* __restrict__ ob,
                                 const float* __restrict__ outW,
                                 const float* __restrict__ outb) {
    int L = blockIdx.x;
    int n = threadIdx.x;
    const float* uw = outW + (size_t)L*EHH*EE;
    const float* obl = ob + (size_t)L*EHH;
    float acc = outb[(size_t)L*EE + n];
    #pragma unroll 8
    for (int j = 0; j < EHH; j++) acc = fmaf(obl[j], uw[(size_t)j*EE + n], acc);
    g_bc[(size_t)L*EE + n] = acc;
}

// ---------------- embed ----------------
__global__ void embed_kernel(const float* __restrict__ str_fea,
                             const int*   __restrict__ comp_fea,
                             const float* __restrict__ atom_table,
                             const float* __restrict__ comp_W,
                             const float* __restrict__ comp_b,
                             const float* __restrict__ pdd_W,
                             const float* __restrict__ pdd_b) {
    int t = blockIdx.x;
    int e = threadIdx.x;
    __shared__ float sa[ADIM];
    __shared__ float ss[KF-1];
    const float* sf = str_fea + (size_t)t*KF;
    int idx = comp_fea[t];
    const float* at = atom_table + (size_t)idx*ADIM;
    for (int j = e; j < ADIM; j += EE) sa[j] = at[j];
    for (int j = e; j < KF-1; j += EE) ss[j] = sf[1+j];
    if (e == 0) g_w[t] = sf[0];
    __syncthreads();
    float acc = comp_b[e] + pdd_b[e];
    #pragma unroll 4
    for (int a = 0; a < ADIM; a++) acc = fmaf(sa[a], comp_W[a*EE + e], acc);
    #pragma unroll 4
    for (int j = 0; j < KF-1; j++) acc = fmaf(ss[j], pdd_W[j*EE + e], acc);
    g_x[(size_t)t*EE + e]     = acc;
    g_xinit[(size_t)t*EE + e] = acc;
}

// ---------------- warp-per-token layernorm -> packed planes ----------------
__global__ void ln_kernel(const float* __restrict__ src1,
                          const float* __restrict__ gam,
                          const float* __restrict__ bet,
                          uint32_t* __restrict__ dsth,
                          uint32_t* __restrict__ dstl) {
    int warp = threadIdx.x >> 5, lane = threadIdx.x & 31;
    int t = blockIdx.x*4 + warp;
    size_t off = (size_t)t*EE + lane*4;
    float4 v = *(const float4*)&src1[off];
    float s = v.x + v.y + v.z + v.w;
    #pragma unroll
    for (int o = 16; o > 0; o >>= 1) s += __shfl_xor_sync(0xffffffffu, s, o);
    float m = s * (1.f/EE);
    float dx = v.x - m, dy = v.y - m, dz = v.z - m, dw = v.w - m;
    float q = dx*dx + dy*dy + dz*dz + dw*dw;
    #pragma unroll
    for (int o = 16; o > 0; o >>= 1) q += __shfl_xor_sync(0xffffffffu, q, o);
    float rstd = rsqrtf(q * (1.f/EE) + 1e-5f);
    const float4 gv = *(const float4*)&gam[lane*4];
    const float4 bv = *(const float4*)&bet[lane*4];
    float r0 = dx*rstd*gv.x + bv.x;
    float r1 = dy*rstd*gv.y + bv.y;
    float r2 = dz*rstd*gv.z + bv.z;
    float r3 = dw*rstd*gv.w + bv.w;
    uint32_t h0, l0, h1, l1;
    bsplit2(r0, r1, h0, l0);
    bsplit2(r2, r3, h1, l1);
    *(uint2*)&dsth[(size_t)t*64 + lane*2] = make_uint2(h0, h1);
    *(uint2*)&dstl[(size_t)t*64 + lane*2] = make_uint2(l0, l1);
}

// ---------------- V transpose+split: g_v [bh][tok][d] -> packed [bh][d][tokpair] ----------------
__global__ void transpose_v_kernel() {
    __shared__ float sv[64][129];
    int bh = blockIdx.y, t0 = blockIdx.x*64;
    int tid = threadIdx.x;
    const float* Vg = g_v + ((size_t)bh*SEQ + t0)*EE;
    #pragma unroll
    for (int i = 0; i < 8; i++) {
        int c = i*256 + tid;               // 0..2047 float4s
        int tok = c >> 5, q = (c & 31)*4;
        const float4 f = *(const float4*)&Vg[(size_t)tok*EE + q];
        sv[tok][q]   = f.x; sv[tok][q+1] = f.y;
        sv[tok][q+2] = f.z; sv[tok][q+3] = f.w;
    }
    __syncthreads();
    uint32_t* oh = g_vth + (size_t)bh*EE*256 + (t0 >> 1);
    uint32_t* ol = g_vtl + (size_t)bh*EE*256 + (t0 >> 1);
    #pragma unroll
    for (int i = 0; i < 16; i++) {
        int widx = i*256 + tid;            // 0..4095
        int d = widx >> 5, tp = widx & 31;
        uint32_t hi, lo;
        bsplit2(sv[2*tp][d], sv[2*tp+1][d], hi, lo);
        oh[(size_t)d*256 + tp] = hi;
        ol[(size_t)d*256 + tp] = lo;
    }
}

// ---------------- pre-split bf16 GEMM (3-mma), cp.async double-buffered ----------------
#define BM 128
#define BN 128
#define GP 20   // smem row pitch in words
#define PL 2560 // plane size: 128*GP

enum { EPI_BIAS_ADD_LN=1, EPI_MISH_ADD_LN=2, EPI_QKV=3 };

template<int EPI>
__global__ __launch_bounds__(256, 2)
void gemm_kernel(const uint32_t* __restrict__ Ah_g, const uint32_t* __restrict__ Al_g, int lda,
                 const uint32_t* __restrict__ Bh_g, const uint32_t* __restrict__ Bl_g, int ldb,
                 float* __restrict__ C, int ldc,
                 uint32_t* __restrict__ Ch, uint32_t* __restrict__ Cl, int ldcw,
                 int K,
                 const float* __restrict__ bias,
                 const float* __restrict__ addend,
                 const float* __restrict__ gam,
                 const float* __restrict__ bet) {
    extern __shared__ uint32_t smx[];
    int bm = blockIdx.y * BM, bn = blockIdx.x * BN;

    int tid  = threadIdx.x;
    int lane = tid & 31;
    int wid  = tid >> 5;
    int warpM = wid & 3;
    int warpN = wid >> 2;
    int g  = lane >> 2;
    int tg = lane & 3;

    float d[2][8][4];
    #pragma unroll
    for (int mt=0; mt<2; mt++)
        #pragma unroll
        for (int nt=0; nt<8; nt++)
            #pragma unroll
            for (int c=0; c<4; c++) d[mt][nt][c] = 0.f;

    int nIter = K >> 5;

    {
        uint32_t* s = smx;
        #pragma unroll
        for (int i = 0; i < 2; i++) {
            int c = i*256 + tid;
            int row = c >> 2, q = (c & 3)*4;
            cp16(&s[0*PL + row*GP + q], Ah_g + (size_t)(bm+row)*lda + q);
            cp16(&s[1*PL + row*GP + q], Al_g + (size_t)(bm+row)*lda + q);
            cp16(&s[2*PL + row*GP + q], Bh_g + (size_t)(bn+row)*ldb + q);
            cp16(&s[3*PL + row*GP + q], Bl_g + (size_t)(bn+row)*ldb + q);
        }
    }
    asm volatile("cp.async.commit_group;" ::: "memory");

    for (int it = 0; it < nIter; it++) {
        asm volatile("cp.async.wait_group 0;" ::: "memory");
        __syncthreads();
        if (it + 1 < nIter) {
            uint32_t* s = smx + ((it+1)&1)*4*PL;
            int kw = (it+1)*16;
            #pragma unroll
            for (int i = 0; i < 2; i++) {
                int c = i*256 + tid;
                int row = c >> 2, q = (c & 3)*4;
                cp16(&s[0*PL + row*GP + q], Ah_g + (size_t)(bm+row)*lda + kw + q);
                cp16(&s[1*PL + row*GP + q], Al_g + (size_t)(bm+row)*lda + kw + q);
                cp16(&s[2*PL + row*GP + q], Bh_g + (size_t)(bn+row)*ldb + kw + q);
                cp16(&s[3*PL + row*GP + q], Bl_g + (size_t)(bn+row)*ldb + kw + q);
            }
            asm volatile("cp.async.commit_group;" ::: "memory");
        }

        const uint32_t* Ah = smx + (it&1)*4*PL;
        const uint32_t* Al = Ah + PL;
        const uint32_t* Bh = Al + PL;
        const uint32_t* Bl = Bh + PL;

        #pragma unroll
        for (int js = 0; js < 2; js++) {
            int kb = js*8 + tg;
            uint32_t ah[2][4], al[2][4];
            #pragma unroll
            for (int mt = 0; mt < 2; mt++) {
                int m0 = warpM*32 + mt*16 + g;
                ah[mt][0] = Ah[m0*GP + kb];       al[mt][0] = Al[m0*GP + kb];
                ah[mt][1] = Ah[(m0+8)*GP + kb];   al[mt][1] = Al[(m0+8)*GP + kb];
                ah[mt][2] = Ah[m0*GP + kb+4];     al[mt][2] = Al[m0*GP + kb+4];
                ah[mt][3] = Ah[(m0+8)*GP + kb+4]; al[mt][3] = Al[(m0+8)*GP + kb+4];
            }
            #pragma unroll
            for (int nt = 0; nt < 8; nt++) {
                int n0 = warpN*64 + nt*8 + g;
                uint32_t bh0 = Bh[n0*GP + kb], bh1 = Bh[n0*GP + kb+4];
                uint32_t bl0 = Bl[n0*GP + kb], bl1 = Bl[n0*GP + kb+4];
                #pragma unroll
                for (int mt = 0; mt < 2; mt++) {
                    mma_bf16(d[mt][nt], ah[mt], bh0, bh1);
                    mma_bf16(d[mt][nt], ah[mt], bl0, bl1);
                    mma_bf16(d[mt][nt], al[mt], bh0, bh1);
                }
            }
        }
    }

    if (EPI == EPI_QKV) {
        #pragma unroll
        for (int mt = 0; mt < 2; mt++) {
            #pragma unroll
            for (int nt = 0; nt < 8; nt++) {
                #pragma unroll
                for (int half = 0; half < 2; half++) {
                    int m = bm + warpM*32 + mt*16 + g + half*8;
                    int n = bn + warpN*64 + nt*8 + 2*tg;
                    float v0 = d[mt][nt][half*2 + 0];
                    float v1 = d[mt][nt][half*2 + 1];
                    int b = m >> 9, tok = m & 511;
                    int hh = n / 384, rem = n % 384;
                    int rr = rem >> 7, dd = rem & 127;
                    size_t bhrow = ((size_t)(b*HH + hh)*SEQ + tok);
                    float x0 = v0 + bias[n], x1 = v1 + bias[n+1];
                    if (rr == 0) {
                        uint32_t hi, lo; bsplit2(x0*SCALE, x1*SCALE, hi, lo);
                        g_qh[bhrow*64 + (dd>>1)] = hi;
                        g_ql[bhrow*64 + (dd>>1)] = lo;
                    } else if (rr == 1) {
                        uint32_t hi, lo; bsplit2(x0, x1, hi, lo);
                        g_kh[bhrow*64 + (dd>>1)] = hi;
                        g_kl[bhrow*64 + (dd>>1)] = lo;
                    } else {
                        *(float2*)&g_v[bhrow*EE + dd] = make_float2(x0, x1);
                    }
                }
            }
        }
    } else {
        // ---- fused row LayerNorm epilogue (full 128-col rows in-block) ----
        // 1) finalize values in-register
        #pragma unroll
        for (int mt = 0; mt < 2; mt++) {
            #pragma unroll
            for (int nt = 0; nt < 8; nt++) {
                #pragma unroll
                for (int half = 0; half < 2; half++) {
                    int m = bm + warpM*32 + mt*16 + g + half*8;
                    int n = warpN*64 + nt*8 + 2*tg;   // bn = 0 always here
                    const float2 ad = *(const float2*)&addend[(size_t)m*ldc + n];
                    float v0 = d[mt][nt][half*2+0] + bias[n];
                    float v1 = d[mt][nt][half*2+1] + bias[n+1];
                    if (EPI == EPI_MISH_ADD_LN) {
                        float s0 = (v0 > 20.f) ? v0 : log1pf(expf(v0));
                        float s1 = (v1 > 20.f) ? v1 : log1pf(expf(v1));
                        v0 = v0 * tanhf(s0);
                        v1 = v1 * tanhf(s1);
                    }
                    d[mt][nt][half*2+0] = v0 + ad.x;
                    d[mt][nt][half*2+1] = v1 + ad.y;
                }
            }
        }
        // 2) row sums / sumsq
        float rs[2][2], rq[2][2];
        #pragma unroll
        for (int mt = 0; mt < 2; mt++)
            #pragma unroll
            for (int half = 0; half < 2; half++) { rs[mt][half]=0.f; rq[mt][half]=0.f; }
        #pragma unroll
        for (int mt = 0; mt < 2; mt++)
            #pragma unroll
            for (int nt = 0; nt < 8; nt++)
                #pragma unroll
                for (int half = 0; half < 2; half++)
                    #pragma unroll
                    for (int j = 0; j < 2; j++) {
                        float v = d[mt][nt][half*2+j];
                        rs[mt][half] += v;
                        rq[mt][half] += v*v;
                    }
        #pragma unroll
        for (int off = 1; off <= 2; off <<= 1) {
            #pragma unroll
            for (int mt = 0; mt < 2; mt++)
                #pragma unroll
                for (int half = 0; half < 2; half++) {
                    rs[mt][half] += __shfl_xor_sync(0xffffffffu, rs[mt][half], off);
                    rq[mt][half] += __shfl_xor_sync(0xffffffffu, rq[mt][half], off);
                }
        }
        __syncthreads();                 // smem tiles no longer needed
        float* sms = (float*)smx;        // [0:256) sums (warpN-major), [256:512) sumsq
        if (tg == 0) {
            #pragma unroll
            for (int mt = 0; mt < 2; mt++)
                #pragma unroll
                for (int half = 0; half < 2; half++) {
                    int rl = warpM*32 + mt*16 + g + half*8;
                    sms[warpN*128 + rl]       = rs[mt][half];
                    sms[256 + warpN*128 + rl] = rq[mt][half];
                }
        }
        __syncthreads();
        float mean[2][2], rstd[2][2];
        #pragma unroll
        for (int mt = 0; mt < 2; mt++)
            #pragma unroll
            for (int half = 0; half < 2; half++) {
                int rl = warpM*32 + mt*16 + g + half*8;
                float st = sms[rl] + sms[128 + rl];
                float qt = sms[256 + rl] + sms[384 + rl];
                float mn = st * (1.f/EE);
                mean[mt][half] = mn;
                rstd[mt][half] = rsqrtf(qt * (1.f/EE) - mn*mn + 1e-5f);
            }
        // 3) outputs
        #pragma unroll
        for (int mt = 0; mt < 2; mt++) {
            #pragma unroll
            for (int nt = 0; nt < 8; nt++) {
                #pragma unroll
                for (int half = 0; half < 2; half++) {
                    int m = bm + warpM*32 + mt*16 + g + half*8;
                    int n = warpN*64 + nt*8 + 2*tg;
                    float v0 = d[mt][nt][half*2+0];
                    float v1 = d[mt][nt][half*2+1];
                    float mn = mean[mt][half], rd = rstd[mt][half];
                    const float2 gv = *(const float2*)&gam[n];
                    const float2 bv = *(const float2*)&bet[n];
                    float r0 = (v0 - mn)*rd*gv.x + bv.x;
                    float r1 = (v1 - mn)*rd*gv.y + bv.y;
                    if (EPI == EPI_BIAS_ADD_LN) {
                        // out1 (pre-LN) + packed xn planes (post-LN)
                        *(float2*)&C[(size_t)m*ldc + n] = make_float2(v0, v1);
                        uint32_t hi, lo; bsplit2(r0, r1, hi, lo);
                        Ch[(size_t)m*ldcw + (n >> 1)] = hi;
                        Cl[(size_t)m*ldcw + (n >> 1)] = lo;
                    } else { // EPI_MISH_ADD_LN: x = LN(out1 + mish(...))
                        *(float2*)&C[(size_t)m*ldc + n] = make_float2(r0, r1);
                    }
                }
            }
        }
    }
}

// ---------------- fused flash attention (32-key tiles, R14-proven) ----------------
#define QP 68   // pitch for [row][d-pair] Q/K tiles
#define VP 20   // pitch for [d][key-pair] V tiles
#define KT 32
#define NKT (SEQ/KT)   // 16

#define OFF_QH 0
#define OFF_QL (OFF_QH + 128*QP)
#define OFF_KH (OFF_QL + 128*QP)
#define OFF_KL (OFF_KH + KT*QP)
#define OFF_VH (OFF_KL + KT*QP)
#define OFF_VL (OFF_VH + 128*VP)
#define OFF_WS (OFF_VL + 128*VP)
#define FLASH_WORDS (OFF_WS + KT)   // 26912 words = 107648 B

__global__ __launch_bounds__(256, 2)
void flash_kernel() {
    extern __shared__ uint32_t smx[];
    uint32_t* Qh = smx + OFF_QH;
    uint32_t* Ql = smx + OFF_QL;
    uint32_t* Kh = smx + OFF_KH;
    uint32_t* Kl = smx + OFF_KL;
    uint32_t* Vh = smx + OFF_VH;
    uint32_t* Vl = smx + OFF_VL;
    float*    ws = (float*)(smx + OFF_WS);

    int qt = blockIdx.x, bh = blockIdx.y;
    int b = bh >> 3, h = bh & 7;
    int tid = threadIdx.x;
    int lane = tid & 31;
    int wid = tid >> 5;
    int g = lane >> 2, tg = lane & 3;

    // Q tile: copy pre-split planes (128 rows x 64 words per plane)
    const uint32_t* Qgh = g_qh + ((size_t)bh*SEQ + qt*128)*64;
    const uint32_t* Qgl = g_ql + ((size_t)bh*SEQ + qt*128)*64;
    #pragma unroll
    for (int i = 0; i < 8; i++) {
        int c = i*256 + tid;               // 0..2047
        int row = c >> 4, q = (c & 15)*4;
        *(uint4*)&Qh[row*QP + q] = *(const uint4*)&Qgh[row*64 + q];
        *(uint4*)&Ql[row*QP + q] = *(const uint4*)&Qgl[row*64 + q];
    }

    int rowg = qt*128 + wid*16 + g;
    bool mq0 = g_w[b*SEQ + rowg]     > 0.f;
    bool mq1 = g_w[b*SEQ + rowg + 8] > 0.f;

    float m_run[2] = {-9.0e15f, -9.0e15f};
    float l_run[2] = {0.f, 0.f};
    float o[16][4];
    #pragma unroll
    for (int dt = 0; dt < 16; dt++)
        #pragma unroll
        for (int c = 0; c < 4; c++) o[dt][c] = 0.f;

    const uint32_t* Vbh = g_vth + (size_t)bh*EE*256;
    const uint32_t* Vbl = g_vtl + (size_t)bh*EE*256;

    for (int kt = 0; kt < NKT; kt++) {
        __syncthreads();
        if (tid < KT) ws[tid] = g_w[b*SEQ + kt*KT + tid];
        // K tile: 32 rows x 64 words per plane
        {
            const uint32_t* Kgh = g_kh + ((size_t)bh*SEQ + kt*KT)*64;
            const uint32_t* Kgl = g_kl + ((size_t)bh*SEQ + kt*KT)*64;
            #pragma unroll
            for (int i = 0; i < 2; i++) {
                int c = i*256 + tid;       // 0..511
                int row = c >> 4, q = (c & 15)*4;
                *(uint4*)&Kh[row*QP + q] = *(const uint4*)&Kgh[row*64 + q];
                *(uint4*)&Kl[row*QP + q] = *(const uint4*)&Kgl[row*64 + q];
            }
        }
        // V tile: 128 d-rows x 16 words per plane (pre-transposed, pre-split)
        #pragma unroll
        for (int i = 0; i < 2; i++) {
            int c = i*256 + tid;           // 0..511
            int dd = c >> 2, q = (c & 3)*4;
            *(uint4*)&Vh[dd*VP + q] = *(const uint4*)&Vbh[(size_t)dd*256 + kt*16 + q];
            *(uint4*)&Vl[dd*VP + q] = *(const uint4*)&Vbl[(size_t)dd*256 + kt*16 + q];
        }
        __syncthreads();

        // ---- S = Q @ K^T (warp: 16 rows x 32 keys) ----
        float s[4][4];
        #pragma unroll
        for (int nt=0; nt<4; nt++)
            #pragma unroll
            for (int c=0; c<4; c++) s[nt][c] = 0.f;

        int m0 = wid*16 + g;
        #pragma unroll
        for (int ks = 0; ks < 8; ks++) {
            int kb = ks*8 + tg;
            uint32_t ah[4], al[4];
            ah[0] = Qh[m0*QP + kb];       al[0] = Ql[m0*QP + kb];
            ah[1] = Qh[(m0+8)*QP + kb];   al[1] = Ql[(m0+8)*QP + kb];
            ah[2] = Qh[m0*QP + kb+4];     al[2] = Ql[m0*QP + kb+4];
            ah[3] = Qh[(m0+8)*QP + kb+4]; al[3] = Ql[(m0+8)*QP + kb+4];
            #pragma unroll
            for (int nt = 0; nt < 4; nt++) {
                int n0 = nt*8 + g;
                uint32_t bh0 = Kh[n0*QP + kb], bh1 = Kh[n0*QP + kb+4];
                uint32_t bl0 = Kl[n0*QP + kb], bl1 = Kl[n0*QP + kb+4];
                mma_bf16(s[nt], ah, bh0, bh1);
                mma_bf16(s[nt], ah, bl0, bl1);
                mma_bf16(s[nt], al, bh0, bh1);
            }
        }

        // ---- mask + online softmax ----
        float tmax[2] = {-9.0e15f, -9.0e15f};
        #pragma unroll
        for (int nt = 0; nt < 4; nt++) {
            int col0 = nt*8 + 2*tg;
            #pragma unroll
            for (int c = 0; c < 4; c++) {
                bool mk = ws[col0 + (c & 1)] > 0.f;
                bool mr = (c < 2) ? mq0 : mq1;
                float v = (mk && mr) ? s[nt][c] : -9.0e15f;
                s[nt][c] = v;
                tmax[c >> 1] = fmaxf(tmax[c >> 1], v);
            }
        }
        #pragma unroll
        for (int off = 1; off <= 2; off <<= 1) {
            tmax[0] = fmaxf(tmax[0], __shfl_xor_sync(0xffffffffu, tmax[0], off));
            tmax[1] = fmaxf(tmax[1], __shfl_xor_sync(0xffffffffu, tmax[1], off));
        }
        float nm0 = fmaxf(m_run[0], tmax[0]);
        float nm1 = fmaxf(m_run[1], tmax[1]);
        float a0 = __expf(m_run[0] - nm0);
        float a1 = __expf(m_run[1] - nm1);
        float rs[2] = {0.f, 0.f};
        #pragma unroll
        for (int nt = 0; nt < 4; nt++) {
            int col0 = nt*8 + 2*tg;
            #pragma unroll
            for (int c = 0; c < 4; c++) {
                float nm = (c < 2) ? nm0 : nm1;
                float p = ws[col0 + (c & 1)] * __expf(s[nt][c] - nm);
                s[nt][c] = p;
                rs[c >> 1] += p;
            }
        }
        #pragma unroll
        for (int off = 1; off <= 2; off <<= 1) {
            rs[0] += __shfl_xor_sync(0xffffffffu, rs[0], off);
            rs[1] += __shfl_xor_sync(0xffffffffu, rs[1], off);
        }
        l_run[0] = a0*l_run[0] + rs[0];
        l_run[1] = a1*l_run[1] + rs[1];
        m_run[0] = nm0; m_run[1] = nm1;
        #pragma unroll
        for (int dt = 0; dt < 16; dt++) {
            o[dt][0] *= a0; o[dt][1] *= a0;
            o[dt][2] *= a1; o[dt][3] *= a1;
        }

        // ---- O += P @ V (2 k16 steps over 32 keys) ----
        #pragma unroll
        for (int j = 0; j < 2; j++) {
            uint32_t pah[4], pal[4];
            bsplit2(s[2*j  ][0], s[2*j  ][1], pah[0], pal[0]);
            bsplit2(s[2*j  ][2], s[2*j  ][3], pah[1], pal[1]);
            bsplit2(s[2*j+1][0], s[2*j+1][1], pah[2], pal[2]);
            bsplit2(s[2*j+1][2], s[2*j+1][3], pah[3], pal[3]);
            int kb = j*8 + tg;
            #pragma unroll
            for (int dt = 0; dt < 16; dt++) {
                int n0 = dt*8 + g;
                uint32_t vh0 = Vh[n0*VP + kb], vh1 = Vh[n0*VP + kb+4];
                uint32_t vl0 = Vl[n0*VP + kb], vl1 = Vl[n0*VP + kb+4];
                mma_bf16(o[dt], pah, vh0, vh1);
                mma_bf16(o[dt], pah, vl0, vl1);
                mma_bf16(o[dt], pal, vh0, vh1);
            }
        }
    }

    // ---- normalize + store split vals planes ----
    float inv0 = 1.f / l_run[0];
    float inv1 = 1.f / l_run[1];
    size_t r0 = (size_t)(b*SEQ) + qt*128 + wid*16 + g;
    size_t r1 = r0 + 8;
    #pragma unroll
    for (int dt = 0; dt < 16; dt++) {
        int w = h*64 + dt*4 + tg;
        uint32_t hi, lo;
        bsplit2(o[dt][0]*inv0, o[dt][1]*inv0, hi, lo);
        g_valsh[r0*512 + w] = hi; g_valsl[r0*512 + w] = lo;
        bsplit2(o[dt][2]*inv1, o[dt][3]*inv1, hi, lo);
        g_valsh[r1*512 + w] = hi; g_valsl[r1*512 + w] = lo;
    }
}

// ---------------- final: weighted pool + LN + head ----------------
__global__ void pool_head_kernel(const float* __restrict__ ln2_g,
                                 const float* __restrict__ ln2_b,
                                 const float* __restrict__ head_W,
                                 const float* __restrict__ head_b,
                                 float* __restrict__ out) {
    __shared__ float sm[4];
    int b = blockIdx.x, e = threadIdx.x;
    const float* xb  = g_x     + (size_t)b*SEQ*EE;
    const float* xib = g_xinit + (size_t)b*SEQ*EE;
    float s = 0.f;
    for (int n = 0; n < SEQ; n++)
        s = fmaf(g_w[b*SEQ + n], xb[n*EE + e] + xib[n*EE + e], s);
    float m = blkSum128(s, sm) * (1.f/EE);
    float d = s - m;
    float var = blkSum128(d*d, sm) * (1.f/EE);
    float p = d * rsqrtf(var + 1e-5f) * ln2_g[e] + ln2_b[e];
    float dot = blkSum128(p * head_W[e], sm);
    if (e == 0) out[b] = dot + head_b[0];
}

// ---------------- host launch ----------------
#define GEMM_SMEM (2*4*PL*4)

extern "C" void kernel_launch(void* const* d_in, const int* in_sizes, int n_in,
                              void* d_out, int out_size) {
    (void)in_sizes; (void)n_in; (void)out_size;
    const float* str_fea   = (const float*)d_in[0];
    const int*   comp_fea  = (const int*)  d_in[1];
    const float* atom_table= (const float*)d_in[3];
    const float* comp_W    = (const float*)d_in[4];
    const float* comp_b    = (const float*)d_in[5];
    const float* pdd_W     = (const float*)d_in[6];
    const float* pdd_b     = (const float*)d_in[7];
    const float* enc_ln_g  = (const float*)d_in[8];
    const float* enc_ln_b  = (const float*)d_in[9];
    const float* qkv_W     = (const float*)d_in[10];
    const float* qkv_b     = (const float*)d_in[11];
    const float* o_W       = (const float*)d_in[12];
    const float* o_b       = (const float*)d_in[13];
    const float* out_W     = (const float*)d_in[14];
    const float* out_b     = (const float*)d_in[15];
    const float* ffn_W     = (const float*)d_in[16];
    const float* ffn_b     = (const float*)d_in[17];
    const float* ln2_g     = (const float*)d_in[18];
    const float* ln2_b     = (const float*)d_in[19];
    const float* head_W    = (const float*)d_in[20];
    const float* head_b    = (const float*)d_in[21];
    float* out = (float*)d_out;

    void* p;
    cudaGetSymbolAddress(&p, g_x);      float* px    = (float*)p;
    cudaGetSymbolAddress(&p, g_out1);   float* pout1 = (float*)p;
    cudaGetSymbolAddress(&p, g_xnh);    uint32_t* pxnh = (uint32_t*)p;
    cudaGetSymbolAddress(&p, g_xnl);    uint32_t* pxnl = (uint32_t*)p;
    cudaGetSymbolAddress(&p, g_valsh);  uint32_t* pvalsh = (uint32_t*)p;
    cudaGetSymbolAddress(&p, g_valsl);  uint32_t* pvalsl = (uint32_t*)p;
    cudaGetSymbolAddress(&p, g_Wqkvh);  uint32_t* pWqkvh = (uint32_t*)p;
    cudaGetSymbolAddress(&p, g_Wqkvl);  uint32_t* pWqkvl = (uint32_t*)p;
    cudaGetSymbolAddress(&p, g_Wffnh);  uint32_t* pWffnh = (uint32_t*)p;
    cudaGetSymbolAddress(&p, g_Wffnl);  uint32_t* pWffnl = (uint32_t*)p;
    cudaGetSymbolAddress(&p, g_Wc);     float* pWc = (float*)p;
    cudaGetSymbolAddress(&p, g_bc);     float* pbc = (float*)p;
    cudaGetSymbolAddress(&p, g_Wch);    uint32_t* pWch = (uint32_t*)p;
    cudaGetSymbolAddress(&p, g_Wcl);    uint32_t* pWcl = (uint32_t*)p;

    cudaFuncSetAttribute(flash_kernel,
        cudaFuncAttributeMaxDynamicSharedMemorySize, FLASH_WORDS * 4);
    cudaFuncSetAttribute(gemm_kernel<EPI_BIAS_ADD_LN>,
        cudaFuncAttributeMaxDynamicSharedMemorySize, GEMM_SMEM);
    cudaFuncSetAttribute(gemm_kernel<EPI_MISH_ADD_LN>,
        cudaFuncAttributeMaxDynamicSharedMemorySize, GEMM_SMEM);
    cudaFuncSetAttribute(gemm_kernel<EPI_QKV>,
        cudaFuncAttributeMaxDynamicSharedMemorySize, GEMM_SMEM);

    // ---- precompute combined o_W@out_W weight + bias, then split ----
    combine_w_kernel<<<dim3(EHH, LL), EE>>>(o_W, out_W);
    combine_b_kernel<<<LL, EE>>>(o_b, out_W, out_b);
    split_weights_kernel<<<dim3((128*512 + 255)/256, LL), 256>>>(
        pWc, pWch, pWcl, EHH, EE);

    // ---- pre-split remaining weights ----
    split_weights_kernel<<<dim3((3072*64 + 255)/256, LL), 256>>>(
        qkv_W, pWqkvh, pWqkvl, EE, 3*EHH);
    split_weights_kernel<<<dim3((128*64 + 255)/256, LL), 256>>>(
        ffn_W, pWffnh, pWffnl, EE, EE);

    embed_kernel<<<TOK, EE>>>(str_fea, comp_fea, atom_table,
                              comp_W, comp_b, pdd_W, pdd_b);

    for (int i = 0; i < LL; i++) {
        const float* g = enc_ln_g + i*EE;
        const float* bta = enc_ln_b + i*EE;

        // xn = LN(x) -> packed planes (layer-start LN)
        ln_kernel<<<TOK/4, 128>>>(px, g, bta, pxnh, pxnl);

        // qkv projection -> packed q (scaled) / packed k / float v
        gemm_kernel<EPI_QKV><<<dim3(3*EHH/BN, TOK/BM), 256, GEMM_SMEM>>>(
            pxnh, pxnl, 64,
            pWqkvh + (size_t)i*3072*64, pWqkvl + (size_t)i*3072*64, 64,
            nullptr, 0, nullptr, nullptr, 0, EE,
            qkv_b + (size_t)i*3*EHH, nullptr, nullptr, nullptr);

        // V -> transposed packed planes
        transpose_v_kernel<<<dim3(SEQ/64, BHH), 256>>>();

        // fused attention -> packed vals planes
        flash_kernel<<<dim3(4, BHH), 256, FLASH_WORDS*4>>>();

        // out1 = x + vals@Wc + bc; fused LN -> out1 float + xn packed
        gemm_kernel<EPI_BIAS_ADD_LN><<<dim3(EE/BN, TOK/BM), 256, GEMM_SMEM>>>(
            pvalsh, pvalsl, 512,
            pWch + (size_t)i*128*512, pWcl + (size_t)i*128*512, 512,
            pout1, EE, pxnh, pxnl, 64, EHH,
            pbc + (size_t)i*EE, px, g, bta);

        // x = LN(out1 + mish(xn @ ffn_W + ffn_b))  [fully fused, out2 never stored]
        gemm_kernel<EPI_MISH_ADD_LN><<<dim3(EE/BN, TOK/BM), 256, GEMM_SMEM>>>(
            pxnh, pxnl, 64,
            pWffnh + (size_t)i*128*64, pWffnl + (size_t)i*128*64, 64,
            px, EE, nullptr, nullptr, 0, EE,
            ffn_b + (size_t)i*EE, pout1, g, bta);
    }

    pool_head_kernel<<<Bb, EE>>>(ln2_g, ln2_b, head_W, head_b, out);
}